// round 3
// baseline (speedup 1.0000x reference)
#include <cuda_runtime.h>
#include <cstdint>

#define Tn 8192
#define Hn 1024
#define In 2816
#define En 8
#define MAXP 17408  // 16384 pairs + up to 8*127 alignment padding, itself 128-aligned

// ------------------- device scratch (no allocations allowed) ---------------
__device__ int   g_cnt[En];
__device__ int   g_cur[En];
__device__ int   g_off[En + 1];
__device__ int   g_eid[Tn * 2];
__device__ float g_ew[Tn * 2];
__device__ int   g_tok[MAXP];
__device__ float g_wt[MAXP];
__device__ int   g_slots[Tn * 2];
__device__ float g_hb[(size_t)MAXP * In];   // silu(gate)*up, tf32-rounded
__device__ float g_po[(size_t)MAXP * Hn];   // per-pair weighted output

// ------------------- small helpers ------------------------------------------
__device__ __forceinline__ uint32_t smem_u32(const void* p) {
    uint32_t a;
    asm("{ .reg .u64 t; cvta.to.shared.u64 t, %1; cvt.u32.u64 %0, t; }" : "=r"(a) : "l"(p));
    return a;
}
__device__ __forceinline__ void cp16(void* sdst, const void* gsrc) {
    uint32_t s = smem_u32(sdst);
    asm volatile("cp.async.cg.shared.global [%0], [%1], 16;\n" :: "r"(s), "l"(gsrc));
}
__device__ __forceinline__ uint32_t f2tf(float x) {
    uint32_t u;
    asm("cvt.rna.tf32.f32 %0, %1;" : "=r"(u) : "f"(x));
    return u;
}
__device__ __forceinline__ void mma8(float* c, const uint32_t* a, const uint32_t* b) {
    asm volatile(
        "mma.sync.aligned.m16n8k8.row.col.f32.tf32.tf32.f32 "
        "{%0,%1,%2,%3}, {%4,%5,%6,%7}, {%8,%9}, {%0,%1,%2,%3};\n"
        : "+f"(c[0]), "+f"(c[1]), "+f"(c[2]), "+f"(c[3])
        : "r"(a[0]), "r"(a[1]), "r"(a[2]), "r"(a[3]), "r"(b[0]), "r"(b[1]));
}

// ------------------- kernel 0: reset per-call state --------------------------
__global__ void k_init() {
    int i = blockIdx.x * blockDim.x + threadIdx.x;
    if (i < En) { g_cnt[i] = 0; g_cur[i] = 0; }
    for (int s = i; s < MAXP; s += gridDim.x * blockDim.x) {
        g_tok[s] = -1;
        g_wt[s] = 0.0f;
    }
}

// ------------------- kernel 1: router (softmax -> top2 -> renorm) ------------
__global__ void k_router(const float* __restrict__ logits) {
    int t = blockIdx.x * blockDim.x + threadIdx.x;
    if (t >= Tn) return;
    float v[En];
#pragma unroll
    for (int e = 0; e < En; e++) v[e] = logits[t * En + e];
    int b0 = 0; float m0 = v[0];
#pragma unroll
    for (int e = 1; e < En; e++) if (v[e] > m0) { m0 = v[e]; b0 = e; }
    int b1 = -1; float m1 = -3.0e38f;
#pragma unroll
    for (int e = 0; e < En; e++) if (e != b0 && v[e] > m1) { m1 = v[e]; b1 = e; }
    // softmax + topk + renormalize collapses to: w0 = 1/(1+exp(l1-l0))
    float e1 = expf(m1 - m0);
    float inv = 1.0f / (1.0f + e1);
    g_eid[2 * t] = b0;  g_ew[2 * t] = inv;
    g_eid[2 * t + 1] = b1; g_ew[2 * t + 1] = e1 * inv;
    atomicAdd(&g_cnt[b0], 1);
    atomicAdd(&g_cnt[b1], 1);
}

// ------------------- kernel 2: 128-aligned exclusive offsets ------------------
__global__ void k_off() {
    if (threadIdx.x == 0 && blockIdx.x == 0) {
        int o = 0;
        g_off[0] = 0;
        for (int e = 0; e < En; e++) {
            o += (g_cnt[e] + 127) & ~127;
            g_off[e + 1] = o;
        }
    }
}

// ------------------- kernel 3: scatter (slot assignment) ----------------------
__global__ void k_scatter() {
    int t = blockIdx.x * blockDim.x + threadIdx.x;
    if (t >= Tn) return;
#pragma unroll
    for (int k = 0; k < 2; k++) {
        int e = g_eid[2 * t + k];
        int pos = atomicAdd(&g_cur[e], 1);
        int s = g_off[e] + pos;
        g_tok[s] = t;
        g_wt[s] = g_ew[2 * t + k];
        g_slots[2 * t + k] = s;
    }
}

// ------------------- GEMM1: h = silu(x W1^T) * (x W3^T), grouped -------------
// Tile: 128 rows (slots) x 128 B-rows (64 gate cols + 64 up cols) -> 64 h cols.
// K = Hn = 1024, K-step 16, double-buffered cp.async. 8 warps (2M x 4N).
__global__ __launch_bounds__(256, 2) void k_gemm1(const float* __restrict__ x,
                                                  const float* __restrict__ w13) {
    __shared__ float sm[10240];  // 40KB: A[2][128][20] + B[2][128][20]
    const int mtile = blockIdx.x, ntile = blockIdx.y;
    const int total = g_off[En];
    if (mtile * 128 >= total) return;
    int e = 0;
#pragma unroll
    for (int i = 0; i < En; i++) if (mtile * 128 >= g_off[i + 1]) e = i + 1;

    float* sA[2] = { sm, sm + 2560 };
    float* sB[2] = { sm + 5120, sm + 7680 };

    const int tid = threadIdx.x;
    const int ar0 = tid >> 2, seg = tid & 3;   // A rows ar0 and ar0+64, 16B segment
    int tokA0 = g_tok[mtile * 128 + ar0];      if (tokA0 < 0) tokA0 = 0;
    int tokA1 = g_tok[mtile * 128 + ar0 + 64]; if (tokA1 < 0) tokA1 = 0;
    const float* aSrc0 = x + (size_t)tokA0 * Hn + seg * 4;
    const float* aSrc1 = x + (size_t)tokA1 * Hn + seg * 4;
    // B rows: ar0 -> gate col (ntile*64+ar0); ar0+64 -> up col (ntile*64+ar0)
    const float* bSrc0 = w13 + ((size_t)e * 2 * In + (size_t)ntile * 64 + ar0) * Hn + seg * 4;
    const float* bSrc1 = w13 + ((size_t)e * 2 * In + In + (size_t)ntile * 64 + ar0) * Hn + seg * 4;

    const int w = tid >> 5, lane = tid & 31;
    const int mBase = (w >> 2) * 64, nBase = (w & 3) * 32;
    const int qr = lane >> 2, qc = lane & 3;

    float acc[4][4][4];
#pragma unroll
    for (int a = 0; a < 4; a++)
#pragma unroll
        for (int b = 0; b < 4; b++)
#pragma unroll
            for (int c = 0; c < 4; c++) acc[a][b][c] = 0.0f;

    // prefetch tile 0
    {
        cp16(&sA[0][ar0 * 20 + seg * 4], aSrc0);
        cp16(&sA[0][(ar0 + 64) * 20 + seg * 4], aSrc1);
        cp16(&sB[0][ar0 * 20 + seg * 4], bSrc0);
        cp16(&sB[0][(ar0 + 64) * 20 + seg * 4], bSrc1);
        asm volatile("cp.async.commit_group;\n" ::: "memory");
    }
    const int NKT = Hn / 16;  // 64
    for (int kt = 0; kt < NKT; kt++) {
        int buf = kt & 1;
        if (kt + 1 < NKT) {
            int k0 = (kt + 1) * 16, nb = buf ^ 1;
            cp16(&sA[nb][ar0 * 20 + seg * 4], aSrc0 + k0);
            cp16(&sA[nb][(ar0 + 64) * 20 + seg * 4], aSrc1 + k0);
            cp16(&sB[nb][ar0 * 20 + seg * 4], bSrc0 + k0);
            cp16(&sB[nb][(ar0 + 64) * 20 + seg * 4], bSrc1 + k0);
            asm volatile("cp.async.commit_group;\n" ::: "memory");
            asm volatile("cp.async.wait_group 1;\n" ::: "memory");
        } else {
            asm volatile("cp.async.wait_group 0;\n" ::: "memory");
        }
        __syncthreads();
        const float* A = sA[buf];
        const float* B = sB[buf];
#pragma unroll
        for (int k8 = 0; k8 < 2; k8++) {
            int k0 = k8 * 8;
            uint32_t af[4][4], bf[4][2];
#pragma unroll
            for (int mi = 0; mi < 4; mi++) {
                int r = mBase + mi * 16 + qr;
                af[mi][0] = f2tf(A[r * 20 + k0 + qc]);
                af[mi][1] = f2tf(A[(r + 8) * 20 + k0 + qc]);
                af[mi][2] = f2tf(A[r * 20 + k0 + 4 + qc]);
                af[mi][3] = f2tf(A[(r + 8) * 20 + k0 + 4 + qc]);
            }
#pragma unroll
            for (int ni = 0; ni < 4; ni++) {
                int c = nBase + ni * 8 + qr;
                bf[ni][0] = f2tf(B[c * 20 + k0 + qc]);
                bf[ni][1] = f2tf(B[c * 20 + k0 + 4 + qc]);
            }
#pragma unroll
            for (int mi = 0; mi < 4; mi++)
#pragma unroll
                for (int ni = 0; ni < 4; ni++) mma8(acc[mi][ni], af[mi], bf[ni]);
        }
        __syncthreads();
    }

    // ---- epilogue: gate warps stage to smem; up warps compute silu(g)*u -> hb
    float* gsm = sm;  // 128 x pitch-66 (8448 floats <= 10240)
    if (nBase < 64) {
#pragma unroll
        for (int mi = 0; mi < 4; mi++)
#pragma unroll
            for (int ni = 0; ni < 4; ni++) {
                int r = mBase + mi * 16 + qr;
                int c = nBase + ni * 8 + qc * 2;
                gsm[r * 66 + c] = acc[mi][ni][0];
                gsm[r * 66 + c + 1] = acc[mi][ni][1];
                gsm[(r + 8) * 66 + c] = acc[mi][ni][2];
                gsm[(r + 8) * 66 + c + 1] = acc[mi][ni][3];
            }
    }
    __syncthreads();
    if (nBase >= 64) {
        size_t rowBase = (size_t)mtile * 128;
#pragma unroll
        for (int mi = 0; mi < 4; mi++)
#pragma unroll
            for (int ni = 0; ni < 4; ni++) {
                int r = mBase + mi * 16 + qr;
                int c = (nBase - 64) + ni * 8 + qc * 2;
#pragma unroll
                for (int half = 0; half < 2; half++) {
                    int rr = r + half * 8;
                    float g0 = gsm[rr * 66 + c];
                    float g1 = gsm[rr * 66 + c + 1];
                    float u0 = acc[mi][ni][half * 2];
                    float u1 = acc[mi][ni][half * 2 + 1];
                    float h0 = g0 * (1.0f / (1.0f + __expf(-g0))) * u0;
                    float h1 = g1 * (1.0f / (1.0f + __expf(-g1))) * u1;
                    float2 v;
                    v.x = __uint_as_float(f2tf(h0));  // pre-round GEMM2 A operand
                    v.y = __uint_as_float(f2tf(h1));
                    *(float2*)&g_hb[(rowBase + rr) * In + (size_t)ntile * 64 + c] = v;
                }
            }
    }
}

// ------------------- GEMM2: po = wt * (h W2^T), grouped ----------------------
// Tile 128 x 128, K = In = 2816, K-step 16.
__global__ __launch_bounds__(256, 2) void k_gemm2(const float* __restrict__ w2) {
    __shared__ float sm[10240];
    const int mtile = blockIdx.x, ntile = blockIdx.y;
    const int total = g_off[En];
    if (mtile * 128 >= total) return;
    int e = 0;
#pragma unroll
    for (int i = 0; i < En; i++) if (mtile * 128 >= g_off[i + 1]) e = i + 1;

    float* sA[2] = { sm, sm + 2560 };
    float* sB[2] = { sm + 5120, sm + 7680 };

    const int tid = threadIdx.x;
    const int ar0 = tid >> 2, seg = tid & 3;
    const float* aSrc0 = g_hb + ((size_t)mtile * 128 + ar0) * In + seg * 4;
    const float* aSrc1 = g_hb + ((size_t)mtile * 128 + ar0 + 64) * In + seg * 4;
    const float* bSrc0 = w2 + ((size_t)e * Hn + (size_t)ntile * 128 + ar0) * In + seg * 4;
    const float* bSrc1 = w2 + ((size_t)e * Hn + (size_t)ntile * 128 + ar0 + 64) * In + seg * 4;

    const int w = tid >> 5, lane = tid & 31;
    const int mBase = (w >> 2) * 64, nBase = (w & 3) * 32;
    const int qr = lane >> 2, qc = lane & 3;

    float acc[4][4][4];
#pragma unroll
    for (int a = 0; a < 4; a++)
#pragma unroll
        for (int b = 0; b < 4; b++)
#pragma unroll
            for (int c = 0; c < 4; c++) acc[a][b][c] = 0.0f;

    {
        cp16(&sA[0][ar0 * 20 + seg * 4], aSrc0);
        cp16(&sA[0][(ar0 + 64) * 20 + seg * 4], aSrc1);
        cp16(&sB[0][ar0 * 20 + seg * 4], bSrc0);
        cp16(&sB[0][(ar0 + 64) * 20 + seg * 4], bSrc1);
        asm volatile("cp.async.commit_group;\n" ::: "memory");
    }
    const int NKT = In / 16;  // 176
    for (int kt = 0; kt < NKT; kt++) {
        int buf = kt & 1;
        if (kt + 1 < NKT) {
            int k0 = (kt + 1) * 16, nb = buf ^ 1;
            cp16(&sA[nb][ar0 * 20 + seg * 4], aSrc0 + k0);
            cp16(&sA[nb][(ar0 + 64) * 20 + seg * 4], aSrc1 + k0);
            cp16(&sB[nb][ar0 * 20 + seg * 4], bSrc0 + k0);
            cp16(&sB[nb][(ar0 + 64) * 20 + seg * 4], bSrc1 + k0);
            asm volatile("cp.async.commit_group;\n" ::: "memory");
            asm volatile("cp.async.wait_group 1;\n" ::: "memory");
        } else {
            asm volatile("cp.async.wait_group 0;\n" ::: "memory");
        }
        __syncthreads();
        const float* A = sA[buf];
        const float* B = sB[buf];
#pragma unroll
        for (int k8 = 0; k8 < 2; k8++) {
            int k0 = k8 * 8;
            uint32_t af[4][4], bf[4][2];
#pragma unroll
            for (int mi = 0; mi < 4; mi++) {
                int r = mBase + mi * 16 + qr;
                // hb values are already exact tf32 — reinterpret, no cvt needed
                af[mi][0] = __float_as_uint(A[r * 20 + k0 + qc]);
                af[mi][1] = __float_as_uint(A[(r + 8) * 20 + k0 + qc]);
                af[mi][2] = __float_as_uint(A[r * 20 + k0 + 4 + qc]);
                af[mi][3] = __float_as_uint(A[(r + 8) * 20 + k0 + 4 + qc]);
            }
#pragma unroll
            for (int ni = 0; ni < 4; ni++) {
                int c = nBase + ni * 8 + qr;
                bf[ni][0] = f2tf(B[c * 20 + k0 + qc]);
                bf[ni][1] = f2tf(B[c * 20 + k0 + 4 + qc]);
            }
#pragma unroll
            for (int mi = 0; mi < 4; mi++)
#pragma unroll
                for (int ni = 0; ni < 4; ni++) mma8(acc[mi][ni], af[mi], bf[ni]);
        }
        __syncthreads();
    }

    // epilogue: scale by router weight, write per-pair output
    size_t rowBase = (size_t)mtile * 128;
#pragma unroll
    for (int mi = 0; mi < 4; mi++) {
        int r = mBase + mi * 16 + qr;
#pragma unroll
        for (int half = 0; half < 2; half++) {
            int rr = r + half * 8;
            float wt = g_wt[rowBase + rr];
#pragma unroll
            for (int ni = 0; ni < 4; ni++) {
                int c = nBase + ni * 8 + qc * 2;
                float2 v;
                v.x = wt * acc[mi][ni][half * 2];
                v.y = wt * acc[mi][ni][half * 2 + 1];
                *(float2*)&g_po[(rowBase + rr) * Hn + (size_t)ntile * 128 + c] = v;
            }
        }
    }
}

// ------------------- combine: out[t] = po[slot0] + po[slot1] -----------------
__global__ void k_combine(float* __restrict__ out) {
    int t = blockIdx.x;
    int i = threadIdx.x;  // 256 threads x float4 = 1024 floats
    int s0 = g_slots[2 * t], s1 = g_slots[2 * t + 1];
    float4 a = *(const float4*)&g_po[(size_t)s0 * Hn + i * 4];
    float4 b = *(const float4*)&g_po[(size_t)s1 * Hn + i * 4];
    float4 o;
    o.x = a.x + b.x; o.y = a.y + b.y; o.z = a.z + b.z; o.w = a.w + b.w;
    *(float4*)&out[(size_t)t * Hn + i * 4] = o;
}

// ------------------- launcher ------------------------------------------------
extern "C" void kernel_launch(void* const* d_in, const int* in_sizes, int n_in,
                              void* d_out, int out_size) {
    const float* x = (const float*)d_in[0];
    const float* logits = (const float*)d_in[1];
    const float* w13 = (const float*)d_in[2];
    const float* w2 = (const float*)d_in[3];
    float* out = (float*)d_out;

    k_init<<<68, 256>>>();                       // 68*256 = 17408 = MAXP
    k_router<<<Tn / 256, 256>>>(logits);
    k_off<<<1, 32>>>();
    k_scatter<<<Tn / 256, 256>>>();
    k_gemm1<<<dim3(MAXP / 128, In / 64), 256>>>(x, w13);   // (136, 44)
    k_gemm2<<<dim3(MAXP / 128, Hn / 128), 256>>>(w2);      // (136, 8)
    k_combine<<<Tn, 256>>>(out);
}

// round 6
// speedup vs baseline: 1.0305x; 1.0305x over previous
#include <cuda_runtime.h>
#include <cstdint>

#define Tn 8192
#define Hn 1024
#define In 2816
#define En 8
#define MAXP 17408  // 16384 pairs + per-expert 128-alignment padding

// ------------------- device scratch (no allocations allowed) -----------------
__device__ int   g_cnt[En];
__device__ int   g_cur[En];
__device__ int   g_off[En + 1];
__device__ int   g_eid[Tn * 2];
__device__ float g_ew[Tn * 2];
__device__ int   g_tok[MAXP];
__device__ float g_wt[MAXP];
__device__ int   g_slots[Tn * 2];
__device__ float g_xg[(size_t)MAXP * Hn];          // gathered x rows, tf32(RNA)
__device__ float g_hb[(size_t)MAXP * In];          // silu(gate)*up, tf32(RNA)
__device__ float g_po[(size_t)MAXP * Hn];          // per-pair weighted output
__device__ float g_w13r[(size_t)En * 2 * In * Hn]; // RNA-rounded w13 (184MB)
__device__ float g_w2r[(size_t)En * Hn * In];      // RNA-rounded w2  (92MB)

// ------------------- helpers -------------------------------------------------
__device__ __forceinline__ uint32_t smem_u32(const void* p) {
    uint32_t a;
    asm("{ .reg .u64 t; cvta.to.shared.u64 t, %1; cvt.u32.u64 %0, t; }" : "=r"(a) : "l"(p));
    return a;
}
__device__ __forceinline__ void cp16(const void* sdst, const void* gsrc) {
    uint32_t s = smem_u32(sdst);
    asm volatile("cp.async.cg.shared.global [%0], [%1], 16;\n" :: "r"(s), "l"(gsrc));
}
__device__ __forceinline__ uint32_t f2tf(float x) {
    uint32_t u;
    asm("cvt.rna.tf32.f32 %0, %1;" : "=r"(u) : "f"(x));
    return u;
}
__device__ __forceinline__ void mma8(float* c, const uint32_t* a, const uint32_t* b) {
    asm volatile(
        "mma.sync.aligned.m16n8k8.row.col.f32.tf32.tf32.f32 "
        "{%0,%1,%2,%3}, {%4,%5,%6,%7}, {%8,%9}, {%0,%1,%2,%3};\n"
        : "+f"(c[0]), "+f"(c[1]), "+f"(c[2]), "+f"(c[3])
        : "r"(a[0]), "r"(a[1]), "r"(a[2]), "r"(a[3]), "r"(b[0]), "r"(b[1]));
}

// smem layout (floats): A0@0 (128x36), A1@4608, B0@9216 (256x36), B1@18432.
// Total 27648 floats = 110,592 B. Epilogue overlays pitch-130 stage (66KB).
static constexpr int SA0 = 0, SA1 = 4608, SB0 = 9216, SB1 = 18432;
static constexpr int SMEM_BYTES = 27648 * 4;

// ------------------- kernel: RNA-round all weights ----------------------------
__global__ void k_roundw(const float* __restrict__ w13, const float* __restrict__ w2) {
    const long N1 = (long)En * 2 * In * Hn / 4;  // float4 count in w13
    const long N2 = (long)En * Hn * In / 4;
    long i = (long)blockIdx.x * blockDim.x + threadIdx.x;
    const long stride = (long)gridDim.x * blockDim.x;
    for (; i < N1 + N2; i += stride) {
        float4 v;
        if (i < N1) v = ((const float4*)w13)[i];
        else        v = ((const float4*)w2)[i - N1];
        v.x = __uint_as_float(f2tf(v.x));
        v.y = __uint_as_float(f2tf(v.y));
        v.z = __uint_as_float(f2tf(v.z));
        v.w = __uint_as_float(f2tf(v.w));
        if (i < N1) ((float4*)g_w13r)[i] = v;
        else        ((float4*)g_w2r)[i - N1] = v;
    }
}

// ------------------- kernel: reset per-call state -----------------------------
__global__ void k_init() {
    int i = blockIdx.x * blockDim.x + threadIdx.x;
    if (i < En) { g_cnt[i] = 0; g_cur[i] = 0; }
    for (int s = i; s < MAXP; s += gridDim.x * blockDim.x) {
        g_tok[s] = -1;
        g_wt[s] = 0.0f;
    }
}

// ------------------- kernel: router ------------------------------------------
__global__ void k_router(const float* __restrict__ logits) {
    int t = blockIdx.x * blockDim.x + threadIdx.x;
    if (t >= Tn) return;
    float v[En];
#pragma unroll
    for (int e = 0; e < En; e++) v[e] = logits[t * En + e];
    int b0 = 0; float m0 = v[0];
#pragma unroll
    for (int e = 1; e < En; e++) if (v[e] > m0) { m0 = v[e]; b0 = e; }
    int b1 = -1; float m1 = -3.0e38f;
#pragma unroll
    for (int e = 0; e < En; e++) if (e != b0 && v[e] > m1) { m1 = v[e]; b1 = e; }
    float e1 = expf(m1 - m0);
    float inv = 1.0f / (1.0f + e1);
    g_eid[2 * t] = b0;     g_ew[2 * t] = inv;
    g_eid[2 * t + 1] = b1; g_ew[2 * t + 1] = e1 * inv;
    atomicAdd(&g_cnt[b0], 1);
    atomicAdd(&g_cnt[b1], 1);
}

// ------------------- kernel: 128-aligned offsets ------------------------------
__global__ void k_off() {
    if (threadIdx.x == 0 && blockIdx.x == 0) {
        int o = 0;
        g_off[0] = 0;
        for (int e = 0; e < En; e++) {
            o += (g_cnt[e] + 127) & ~127;
            g_off[e + 1] = o;
        }
    }
}

// ------------------- kernel: scatter ------------------------------------------
__global__ void k_scatter() {
    int t = blockIdx.x * blockDim.x + threadIdx.x;
    if (t >= Tn) return;
#pragma unroll
    for (int k = 0; k < 2; k++) {
        int e = g_eid[2 * t + k];
        int pos = atomicAdd(&g_cur[e], 1);
        int s = g_off[e] + pos;
        g_tok[s] = t;
        g_wt[s] = g_ew[2 * t + k];
        g_slots[2 * t + k] = s;
    }
}

// ------------------- kernel: gather x rows (tf32-rounded) ---------------------
__global__ void k_gather(const float* __restrict__ x) {
    int s = blockIdx.x;
    int tok = g_tok[s];
    float4 v = make_float4(0.f, 0.f, 0.f, 0.f);
    if (tok >= 0) {
        v = *(const float4*)&x[(size_t)tok * Hn + threadIdx.x * 4];
        v.x = __uint_as_float(f2tf(v.x));
        v.y = __uint_as_float(f2tf(v.y));
        v.z = __uint_as_float(f2tf(v.z));
        v.w = __uint_as_float(f2tf(v.w));
    }
    *(float4*)&g_xg[(size_t)s * Hn + threadIdx.x * 4] = v;
}

// =============================================================================
// GEMM1: h = silu(x W1^T) * (x W3^T).  CTA tile M=128 slots x 256 B-rows
// (rows 0..127 = gate cols n0..n0+127, rows 128..255 = up cols).
// 8 warps of 64x64.  K = Hn, chunk = 32, double-buffered cp.async, zero CVT.
// =============================================================================
__global__ __launch_bounds__(256, 1) void k_gemm1() {
    extern __shared__ float sm[];
    const int mtile = blockIdx.x, ntile = blockIdx.y;  // mtile fast (A L2-reuse)
    if (mtile * 128 >= g_off[En]) return;
    int e = 0;
#pragma unroll
    for (int i = 0; i < En; i++) if (mtile * 128 >= g_off[i + 1]) e = i + 1;
    const int n0 = ntile * 128;  // h-column base (gate & up share index)
    const int tid = threadIdx.x;

    // loader slots: A 4x16B/thread/chunk, B 8x16B/thread/chunk
    const float* pA[4]; int oA[4];
    const float* pB[8]; int oB[8];
#pragma unroll
    for (int q = 0; q < 4; q++) {
        int u = tid + q * 256, r = u >> 3, sg = u & 7;
        pA[q] = g_xg + (size_t)(mtile * 128 + r) * Hn + sg * 4;
        oA[q] = r * 36 + sg * 4;
    }
#pragma unroll
    for (int q = 0; q < 8; q++) {
        int u = tid + q * 256, r = u >> 3, sg = u & 7;
        pB[q] = (r < 128)
            ? (g_w13r + ((size_t)e * 2 * In + n0 + r) * Hn + sg * 4)
            : (g_w13r + ((size_t)e * 2 * In + In + n0 + (r - 128)) * Hn + sg * 4);
        oB[q] = r * 36 + sg * 4;
    }
    float* Ab[2] = { sm + SA0, sm + SA1 };
    float* Bb[2] = { sm + SB0, sm + SB1 };

    const int w = tid >> 5, lane = tid & 31;
    const int mBase = (w & 1) * 64, nBase = (w >> 1) * 64;
    const int qr = lane >> 2, qc = lane & 3;

    float acc[4][8][4];
#pragma unroll
    for (int a = 0; a < 4; a++)
#pragma unroll
        for (int b = 0; b < 8; b++)
#pragma unroll
            for (int c = 0; c < 4; c++) acc[a][b][c] = 0.0f;

#pragma unroll
    for (int c = 0; c < 2; c++) {  // prologue: chunks 0,1
#pragma unroll
        for (int q = 0; q < 4; q++) cp16(&Ab[c][oA[q]], pA[q] + c * 32);
#pragma unroll
        for (int q = 0; q < 8; q++) cp16(&Bb[c][oB[q]], pB[q] + c * 32);
        asm volatile("cp.async.commit_group;" ::: "memory");
    }
    const int NC = Hn / 32;  // 32
    for (int i = 0; i < NC; i++) {
        const int s = i & 1;
        asm volatile("cp.async.wait_group 1;" ::: "memory");
        __syncthreads();
        const float* A = Ab[s];
        const float* B = Bb[s];
#pragma unroll
        for (int k8 = 0; k8 < 4; k8++) {
            int k0 = k8 * 8;
            uint32_t af[4][4], bf[8][2];
#pragma unroll
            for (int mi = 0; mi < 4; mi++) {
                int r = mBase + mi * 16 + qr;
                af[mi][0] = __float_as_uint(A[r * 36 + k0 + qc]);
                af[mi][1] = __float_as_uint(A[(r + 8) * 36 + k0 + qc]);
                af[mi][2] = __float_as_uint(A[r * 36 + k0 + 4 + qc]);
                af[mi][3] = __float_as_uint(A[(r + 8) * 36 + k0 + 4 + qc]);
            }
#pragma unroll
            for (int ni = 0; ni < 8; ni++) {
                int c = nBase + ni * 8 + qr;
                bf[ni][0] = __float_as_uint(B[c * 36 + k0 + qc]);
                bf[ni][1] = __float_as_uint(B[c * 36 + k0 + 4 + qc]);
            }
#pragma unroll
            for (int mi = 0; mi < 4; mi++)
#pragma unroll
                for (int ni = 0; ni < 8; ni++) mma8(acc[mi][ni], af[mi], bf[ni]);
        }
        __syncthreads();
        if (i + 2 < NC) {
#pragma unroll
            for (int q = 0; q < 4; q++) cp16(&Ab[s][oA[q]], pA[q] + (i + 2) * 32);
#pragma unroll
            for (int q = 0; q < 8; q++) cp16(&Bb[s][oB[q]], pB[q] + (i + 2) * 32);
        }
        asm volatile("cp.async.commit_group;" ::: "memory");
    }

    // ---- epilogue: gate warps stage; up warps compute silu(g)*u -> g_hb ------
    float* sE = sm;  // 128 x pitch-130 (66,560B <= 110,592)
    if (nBase < 128) {
#pragma unroll
        for (int mi = 0; mi < 4; mi++)
#pragma unroll
            for (int ni = 0; ni < 8; ni++) {
                int r = mBase + mi * 16 + qr;
                int c = nBase + ni * 8 + qc * 2;
                sE[r * 130 + c] = acc[mi][ni][0];
                sE[r * 130 + c + 1] = acc[mi][ni][1];
                sE[(r + 8) * 130 + c] = acc[mi][ni][2];
                sE[(r + 8) * 130 + c + 1] = acc[mi][ni][3];
            }
    }
    __syncthreads();
    if (nBase >= 128) {
        const size_t rowBase = (size_t)mtile * 128;
#pragma unroll
        for (int mi = 0; mi < 4; mi++)
#pragma unroll
            for (int ni = 0; ni < 8; ni++) {
                int j = (nBase - 128) + ni * 8 + qc * 2;
#pragma unroll
                for (int half = 0; half < 2; half++) {
                    int r = mBase + mi * 16 + qr + half * 8;
                    float g0 = sE[r * 130 + j];
                    float g1 = sE[r * 130 + j + 1];
                    float u0 = acc[mi][ni][half * 2];
                    float u1 = acc[mi][ni][half * 2 + 1];
                    float h0 = g0 * (1.0f / (1.0f + __expf(-g0))) * u0;
                    float h1 = g1 * (1.0f / (1.0f + __expf(-g1))) * u1;
                    float2 v;
                    v.x = __uint_as_float(f2tf(h0));
                    v.y = __uint_as_float(f2tf(h1));
                    *(float2*)&g_hb[(rowBase + r) * In + (size_t)n0 + j] = v;
                }
            }
    }
}

// =============================================================================
// GEMM2: po = wt * (h W2^T).  CTA tile M=128 x N=256 out cols, K = In.
// Same structure; ntile-fast raster keeps w2 (92MB) L2-resident.
// =============================================================================
__global__ __launch_bounds__(256, 1) void k_gemm2() {
    extern __shared__ float sm[];
    const int ntile = blockIdx.x, mtile = blockIdx.y;  // ntile fast
    if (mtile * 128 >= g_off[En]) return;
    int e = 0;
#pragma unroll
    for (int i = 0; i < En; i++) if (mtile * 128 >= g_off[i + 1]) e = i + 1;
    const int n0 = ntile * 256;
    const int tid = threadIdx.x;

    const float* pA[4]; int oA[4];
    const float* pB[8]; int oB[8];
#pragma unroll
    for (int q = 0; q < 4; q++) {
        int u = tid + q * 256, r = u >> 3, sg = u & 7;
        pA[q] = g_hb + (size_t)(mtile * 128 + r) * In + sg * 4;
        oA[q] = r * 36 + sg * 4;
    }
#pragma unroll
    for (int q = 0; q < 8; q++) {
        int u = tid + q * 256, r = u >> 3, sg = u & 7;
        pB[q] = g_w2r + ((size_t)e * Hn + n0 + r) * In + sg * 4;
        oB[q] = r * 36 + sg * 4;
    }
    float* Ab[2] = { sm + SA0, sm + SA1 };
    float* Bb[2] = { sm + SB0, sm + SB1 };

    const int w = tid >> 5, lane = tid & 31;
    const int mBase = (w & 1) * 64, nBase = (w >> 1) * 64;
    const int qr = lane >> 2, qc = lane & 3;

    float acc[4][8][4];
#pragma unroll
    for (int a = 0; a < 4; a++)
#pragma unroll
        for (int b = 0; b < 8; b++)
#pragma unroll
            for (int c = 0; c < 4; c++) acc[a][b][c] = 0.0f;

#pragma unroll
    for (int c = 0; c < 2; c++) {
#pragma unroll
        for (int q = 0; q < 4; q++) cp16(&Ab[c][oA[q]], pA[q] + c * 32);
#pragma unroll
        for (int q = 0; q < 8; q++) cp16(&Bb[c][oB[q]], pB[q] + c * 32);
        asm volatile("cp.async.commit_group;" ::: "memory");
    }
    const int NC = In / 32;  // 88
    for (int i = 0; i < NC; i++) {
        const int s = i & 1;
        asm volatile("cp.async.wait_group 1;" ::: "memory");
        __syncthreads();
        const float* A = Ab[s];
        const float* B = Bb[s];
#pragma unroll
        for (int k8 = 0; k8 < 4; k8++) {
            int k0 = k8 * 8;
            uint32_t af[4][4], bf[8][2];
#pragma unroll
            for (int mi = 0; mi < 4; mi++) {
                int r = mBase + mi * 16 + qr;
                af[mi][0] = __float_as_uint(A[r * 36 + k0 + qc]);
                af[mi][1] = __float_as_uint(A[(r + 8) * 36 + k0 + qc]);
                af[mi][2] = __float_as_uint(A[r * 36 + k0 + 4 + qc]);
                af[mi][3] = __float_as_uint(A[(r + 8) * 36 + k0 + 4 + qc]);
            }
#pragma unroll
            for (int ni = 0; ni < 8; ni++) {
                int c = nBase + ni * 8 + qr;
                bf[ni][0] = __float_as_uint(B[c * 36 + k0 + qc]);
                bf[ni][1] = __float_as_uint(B[c * 36 + k0 + 4 + qc]);
            }
#pragma unroll
            for (int mi = 0; mi < 4; mi++)
#pragma unroll
                for (int ni = 0; ni < 8; ni++) mma8(acc[mi][ni], af[mi], bf[ni]);
        }
        __syncthreads();
        if (i + 2 < NC) {
#pragma unroll
            for (int q = 0; q < 4; q++) cp16(&Ab[s][oA[q]], pA[q] + (i + 2) * 32);
#pragma unroll
            for (int q = 0; q < 8; q++) cp16(&Bb[s][oB[q]], pB[q] + (i + 2) * 32);
        }
        asm volatile("cp.async.commit_group;" ::: "memory");
    }

    // ---- epilogue: scale by router weight, write per-pair output -------------
    const size_t rowBase = (size_t)mtile * 128;
#pragma unroll
    for (int mi = 0; mi < 4; mi++) {
#pragma unroll
        for (int half = 0; half < 2; half++) {
            int r = mBase + mi * 16 + qr + half * 8;
            float wt = g_wt[rowBase + r];
#pragma unroll
            for (int ni = 0; ni < 8; ni++) {
                int c = nBase + ni * 8 + qc * 2;
                float2 v;
                v.x = wt * acc[mi][ni][half * 2];
                v.y = wt * acc[mi][ni][half * 2 + 1];
                *(float2*)&g_po[(rowBase + r) * Hn + (size_t)n0 + c] = v;
            }
        }
    }
}

// ------------------- combine: out[t] = po[slot0] + po[slot1] ------------------
__global__ void k_combine(float* __restrict__ out) {
    int t = blockIdx.x;
    int i = threadIdx.x;
    int s0 = g_slots[2 * t], s1 = g_slots[2 * t + 1];
    float4 a = *(const float4*)&g_po[(size_t)s0 * Hn + i * 4];
    float4 b = *(const float4*)&g_po[(size_t)s1 * Hn + i * 4];
    float4 o;
    o.x = a.x + b.x; o.y = a.y + b.y; o.z = a.z + b.z; o.w = a.w + b.w;
    *(float4*)&out[(size_t)t * Hn + i * 4] = o;
}

// ------------------- launcher -------------------------------------------------
extern "C" void kernel_launch(void* const* d_in, const int* in_sizes, int n_in,
                              void* d_out, int out_size) {
    const float* x      = (const float*)d_in[0];
    const float* logits = (const float*)d_in[1];
    const float* w13    = (const float*)d_in[2];
    const float* w2     = (const float*)d_in[3];
    float* out = (float*)d_out;

    cudaFuncSetAttribute(k_gemm1, cudaFuncAttributeMaxDynamicSharedMemorySize, SMEM_BYTES);
    cudaFuncSetAttribute(k_gemm2, cudaFuncAttributeMaxDynamicSharedMemorySize, SMEM_BYTES);

    k_roundw<<<2048, 256>>>(w13, w2);
    k_init<<<68, 256>>>();
    k_router<<<Tn / 256, 256>>>(logits);
    k_off<<<1, 32>>>();
    k_scatter<<<Tn / 256, 256>>>();
    k_gather<<<MAXP, 256>>>(x);
    k_gemm1<<<dim3(MAXP / 128, In / 128), 256, SMEM_BYTES>>>();  // (136, 22)
    k_gemm2<<<dim3(Hn / 256, MAXP / 128), 256, SMEM_BYTES>>>();  // (4, 136)
    k_combine<<<Tn, 256>>>(out);
}

// round 7
// speedup vs baseline: 1.8100x; 1.7564x over previous
#include <cuda_runtime.h>
#include <cuda_fp16.h>
#include <cstdint>

#define Tn 8192
#define Hn 1024
#define In 2816
#define En 8
#define MAXP 17408  // 16384 pairs + per-expert 128-alignment padding

// ------------------- device scratch (no allocations allowed) -----------------
__device__ int    g_cnt[En];
__device__ int    g_cur[En];
__device__ int    g_off[En + 1];
__device__ int    g_eid[Tn * 2];
__device__ float  g_ew[Tn * 2];
__device__ int    g_tok[MAXP];
__device__ float  g_wt[MAXP];
__device__ int    g_slots[Tn * 2];
__device__ __half g_xh[(size_t)MAXP * Hn];           // gathered x rows, fp16
__device__ __half g_hbh[(size_t)MAXP * In];          // silu(gate)*up, fp16
__device__ float  g_po[(size_t)MAXP * Hn];           // per-pair weighted output
__device__ __half g_w13h[(size_t)En * 2 * In * Hn];  // fp16 w13 (92MB)
__device__ __half g_w2h[(size_t)En * Hn * In];       // fp16 w2  (46MB)

// ------------------- helpers -------------------------------------------------
__device__ __forceinline__ uint32_t smem_u32(const void* p) {
    uint32_t a;
    asm("{ .reg .u64 t; cvta.to.shared.u64 t, %1; cvt.u32.u64 %0, t; }" : "=r"(a) : "l"(p));
    return a;
}
__device__ __forceinline__ void cp16(const void* sdst, const void* gsrc) {
    uint32_t s = smem_u32(sdst);
    asm volatile("cp.async.cg.shared.global [%0], [%1], 16;\n" :: "r"(s), "l"(gsrc));
}
// fp16 m16n8k16 mma, fp32 accumulate
__device__ __forceinline__ void mma16(float* c, const uint32_t* a, const uint32_t* b) {
    asm volatile(
        "mma.sync.aligned.m16n8k16.row.col.f32.f16.f16.f32 "
        "{%0,%1,%2,%3}, {%4,%5,%6,%7}, {%8,%9}, {%0,%1,%2,%3};\n"
        : "+f"(c[0]), "+f"(c[1]), "+f"(c[2]), "+f"(c[3])
        : "r"(a[0]), "r"(a[1]), "r"(a[2]), "r"(a[3]), "r"(b[0]), "r"(b[1]));
}
__device__ __forceinline__ uint32_t lds32(const __half* sh, int idx) {
    return *(const uint32_t*)(sh + idx);
}

// smem (halves, pitch 72 per 64-half row): A0@0, A1@9216, B0@18432, B1@36864
static constexpr int SA0 = 0, SA1 = 9216, SB0 = 18432, SB1 = 36864;
static constexpr int SMEM_BYTES = 55296 * 2;  // 110,592 B

// ------------------- kernel: convert weights to fp16 --------------------------
__global__ void k_cvtw(const float* __restrict__ w13, const float* __restrict__ w2) {
    const long N1 = (long)En * 2 * In * Hn / 4;
    const long N2 = (long)En * Hn * In / 4;
    long i = (long)blockIdx.x * blockDim.x + threadIdx.x;
    const long stride = (long)gridDim.x * blockDim.x;
    for (; i < N1 + N2; i += stride) {
        float4 v = (i < N1) ? ((const float4*)w13)[i] : ((const float4*)w2)[i - N1];
        __half2 lo = __floats2half2_rn(v.x, v.y);
        __half2 hi = __floats2half2_rn(v.z, v.w);
        uint2 pk = { *(uint32_t*)&lo, *(uint32_t*)&hi };
        if (i < N1) ((uint2*)g_w13h)[i] = pk;
        else        ((uint2*)g_w2h)[i - N1] = pk;
    }
}

// ------------------- kernel: reset per-call state -----------------------------
__global__ void k_init() {
    int i = blockIdx.x * blockDim.x + threadIdx.x;
    if (i < En) { g_cnt[i] = 0; g_cur[i] = 0; }
    for (int s = i; s < MAXP; s += gridDim.x * blockDim.x) {
        g_tok[s] = -1;
        g_wt[s] = 0.0f;
    }
}

// ------------------- kernel: router ------------------------------------------
__global__ void k_router(const float* __restrict__ logits) {
    int t = blockIdx.x * blockDim.x + threadIdx.x;
    if (t >= Tn) return;
    float v[En];
#pragma unroll
    for (int e = 0; e < En; e++) v[e] = logits[t * En + e];
    int b0 = 0; float m0 = v[0];
#pragma unroll
    for (int e = 1; e < En; e++) if (v[e] > m0) { m0 = v[e]; b0 = e; }
    int b1 = -1; float m1 = -3.0e38f;
#pragma unroll
    for (int e = 0; e < En; e++) if (e != b0 && v[e] > m1) { m1 = v[e]; b1 = e; }
    float e1 = expf(m1 - m0);
    float inv = 1.0f / (1.0f + e1);
    g_eid[2 * t] = b0;     g_ew[2 * t] = inv;
    g_eid[2 * t + 1] = b1; g_ew[2 * t + 1] = e1 * inv;
    atomicAdd(&g_cnt[b0], 1);
    atomicAdd(&g_cnt[b1], 1);
}

// ------------------- kernel: 128-aligned offsets ------------------------------
__global__ void k_off() {
    if (threadIdx.x == 0 && blockIdx.x == 0) {
        int o = 0;
        g_off[0] = 0;
        for (int e = 0; e < En; e++) {
            o += (g_cnt[e] + 127) & ~127;
            g_off[e + 1] = o;
        }
    }
}

// ------------------- kernel: scatter ------------------------------------------
__global__ void k_scatter() {
    int t = blockIdx.x * blockDim.x + threadIdx.x;
    if (t >= Tn) return;
#pragma unroll
    for (int k = 0; k < 2; k++) {
        int e = g_eid[2 * t + k];
        int pos = atomicAdd(&g_cur[e], 1);
        int s = g_off[e] + pos;
        g_tok[s] = t;
        g_wt[s] = g_ew[2 * t + k];
        g_slots[2 * t + k] = s;
    }
}

// ------------------- kernel: gather x rows -> fp16 ----------------------------
__global__ void k_gather(const float* __restrict__ x) {
    int s = blockIdx.x;
    int tok = g_tok[s];
    uint2 pk = { 0u, 0u };
    if (tok >= 0) {
        float4 v = *(const float4*)&x[(size_t)tok * Hn + threadIdx.x * 4];
        __half2 lo = __floats2half2_rn(v.x, v.y);
        __half2 hi = __floats2half2_rn(v.z, v.w);
        pk.x = *(uint32_t*)&lo;
        pk.y = *(uint32_t*)&hi;
    }
    *(uint2*)&g_xh[(size_t)s * Hn + threadIdx.x * 4] = pk;
}

// =============================================================================
// GEMM1: h = silu(x W1^T) * (x W3^T).  CTA tile M=128 slots x 256 B-rows
// (rows 0..127 = gate cols n0..n0+127, rows 128..255 = up cols).
// fp16 m16n8k16, K-chunk = 64 halves (128B/row), pitch-72 smem, 8 warps 64x64.
// =============================================================================
__global__ __launch_bounds__(256, 1) void k_gemm1() {
    extern __shared__ __align__(16) char smraw[];
    __half* sh = (__half*)smraw;
    const int mtile = blockIdx.x, ntile = blockIdx.y;  // mtile fast (A L2-reuse)
    if (mtile * 128 >= g_off[En]) return;
    int e = 0;
#pragma unroll
    for (int i = 0; i < En; i++) if (mtile * 128 >= g_off[i + 1]) e = i + 1;
    const int n0 = ntile * 128;
    const int tid = threadIdx.x;

    // loaders: chunk = 64 halves/row. A:128 rows x 8 seg(16B) = 4/thread.
    // B: 256 rows x 8 seg = 8/thread.
    const __half* pA[4]; int oA[4];
    const __half* pB[8]; int oB[8];
#pragma unroll
    for (int q = 0; q < 4; q++) {
        int u = tid + q * 256, r = u >> 3, sg = u & 7;
        pA[q] = g_xh + (size_t)(mtile * 128 + r) * Hn + sg * 8;
        oA[q] = r * 72 + sg * 8;
    }
#pragma unroll
    for (int q = 0; q < 8; q++) {
        int u = tid + q * 256, r = u >> 3, sg = u & 7;
        pB[q] = (r < 128)
            ? (g_w13h + ((size_t)e * 2 * In + n0 + r) * Hn + sg * 8)
            : (g_w13h + ((size_t)e * 2 * In + In + n0 + (r - 128)) * Hn + sg * 8);
        oB[q] = r * 72 + sg * 8;
    }
    __half* Ab[2] = { sh + SA0, sh + SA1 };
    __half* Bb[2] = { sh + SB0, sh + SB1 };

    const int w = tid >> 5, lane = tid & 31;
    const int mBase = (w & 1) * 64, nBase = (w >> 1) * 64;
    const int qr = lane >> 2, qc = lane & 3;

    float acc[4][8][4];
#pragma unroll
    for (int a = 0; a < 4; a++)
#pragma unroll
        for (int b = 0; b < 8; b++)
#pragma unroll
            for (int c = 0; c < 4; c++) acc[a][b][c] = 0.0f;

#pragma unroll
    for (int c = 0; c < 2; c++) {  // prologue: chunks 0,1
#pragma unroll
        for (int q = 0; q < 4; q++) cp16(&Ab[c][oA[q]], pA[q] + c * 64);
#pragma unroll
        for (int q = 0; q < 8; q++) cp16(&Bb[c][oB[q]], pB[q] + c * 64);
        asm volatile("cp.async.commit_group;" ::: "memory");
    }
    const int NC = Hn / 64;  // 16
    for (int i = 0; i < NC; i++) {
        const int s = i & 1;
        asm volatile("cp.async.wait_group 1;" ::: "memory");
        __syncthreads();
        const __half* A = Ab[s];
        const __half* B = Bb[s];
#pragma unroll
        for (int ks = 0; ks < 4; ks++) {
            int k0 = ks * 16;
            uint32_t af[4][4], bf[8][2];
#pragma unroll
            for (int mi = 0; mi < 4; mi++) {
                int r = mBase + mi * 16 + qr;
                af[mi][0] = lds32(A, r * 72 + k0 + qc * 2);
                af[mi][1] = lds32(A, (r + 8) * 72 + k0 + qc * 2);
                af[mi][2] = lds32(A, r * 72 + k0 + qc * 2 + 8);
                af[mi][3] = lds32(A, (r + 8) * 72 + k0 + qc * 2 + 8);
            }
#pragma unroll
            for (int ni = 0; ni < 8; ni++) {
                int c = nBase + ni * 8 + qr;
                bf[ni][0] = lds32(B, c * 72 + k0 + qc * 2);
                bf[ni][1] = lds32(B, c * 72 + k0 + qc * 2 + 8);
            }
#pragma unroll
            for (int mi = 0; mi < 4; mi++)
#pragma unroll
                for (int ni = 0; ni < 8; ni++) mma16(acc[mi][ni], af[mi], bf[ni]);
        }
        __syncthreads();
        if (i + 2 < NC) {
#pragma unroll
            for (int q = 0; q < 4; q++) cp16(&Ab[s][oA[q]], pA[q] + (i + 2) * 64);
#pragma unroll
            for (int q = 0; q < 8; q++) cp16(&Bb[s][oB[q]], pB[q] + (i + 2) * 64);
        }
        asm volatile("cp.async.commit_group;" ::: "memory");
    }

    // ---- epilogue: gate warps stage to smem; up warps compute silu(g)*u ------
    float* sE = (float*)smraw;  // 128 x pitch-130 floats = 66,560 B (fits)
    if (nBase < 128) {
#pragma unroll
        for (int mi = 0; mi < 4; mi++)
#pragma unroll
            for (int ni = 0; ni < 8; ni++) {
                int r = mBase + mi * 16 + qr;
                int c = nBase + ni * 8 + qc * 2;
                sE[r * 130 + c] = acc[mi][ni][0];
                sE[r * 130 + c + 1] = acc[mi][ni][1];
                sE[(r + 8) * 130 + c] = acc[mi][ni][2];
                sE[(r + 8) * 130 + c + 1] = acc[mi][ni][3];
            }
    }
    __syncthreads();
    if (nBase >= 128) {
        const size_t rowBase = (size_t)mtile * 128;
#pragma unroll
        for (int mi = 0; mi < 4; mi++)
#pragma unroll
            for (int ni = 0; ni < 8; ni++) {
                int j = (nBase - 128) + ni * 8 + qc * 2;
#pragma unroll
                for (int half = 0; half < 2; half++) {
                    int r = mBase + mi * 16 + qr + half * 8;
                    float g0 = sE[r * 130 + j];
                    float g1 = sE[r * 130 + j + 1];
                    float u0 = acc[mi][ni][half * 2];
                    float u1 = acc[mi][ni][half * 2 + 1];
                    float h0 = g0 * (1.0f / (1.0f + __expf(-g0))) * u0;
                    float h1 = g1 * (1.0f / (1.0f + __expf(-g1))) * u1;
                    __half2 hv = __floats2half2_rn(h0, h1);
                    *(__half2*)&g_hbh[(rowBase + r) * In + (size_t)n0 + j] = hv;
                }
            }
    }
}

// =============================================================================
// GEMM2: po = wt * (h W2^T).  CTA tile M=128 x N=256 out cols, K = In (fp16).
// =============================================================================
__global__ __launch_bounds__(256, 1) void k_gemm2() {
    extern __shared__ __align__(16) char smraw[];
    __half* sh = (__half*)smraw;
    const int ntile = blockIdx.x, mtile = blockIdx.y;  // ntile fast (w2 L2-resident)
    if (mtile * 128 >= g_off[En]) return;
    int e = 0;
#pragma unroll
    for (int i = 0; i < En; i++) if (mtile * 128 >= g_off[i + 1]) e = i + 1;
    const int n0 = ntile * 256;
    const int tid = threadIdx.x;

    const __half* pA[4]; int oA[4];
    const __half* pB[8]; int oB[8];
#pragma unroll
    for (int q = 0; q < 4; q++) {
        int u = tid + q * 256, r = u >> 3, sg = u & 7;
        pA[q] = g_hbh + (size_t)(mtile * 128 + r) * In + sg * 8;
        oA[q] = r * 72 + sg * 8;
    }
#pragma unroll
    for (int q = 0; q < 8; q++) {
        int u = tid + q * 256, r = u >> 3, sg = u & 7;
        pB[q] = g_w2h + ((size_t)e * Hn + n0 + r) * In + sg * 8;
        oB[q] = r * 72 + sg * 8;
    }
    __half* Ab[2] = { sh + SA0, sh + SA1 };
    __half* Bb[2] = { sh + SB0, sh + SB1 };

    const int w = tid >> 5, lane = tid & 31;
    const int mBase = (w & 1) * 64, nBase = (w >> 1) * 64;
    const int qr = lane >> 2, qc = lane & 3;

    float acc[4][8][4];
#pragma unroll
    for (int a = 0; a < 4; a++)
#pragma unroll
        for (int b = 0; b < 8; b++)
#pragma unroll
            for (int c = 0; c < 4; c++) acc[a][b][c] = 0.0f;

#pragma unroll
    for (int c = 0; c < 2; c++) {
#pragma unroll
        for (int q = 0; q < 4; q++) cp16(&Ab[c][oA[q]], pA[q] + c * 64);
#pragma unroll
        for (int q = 0; q < 8; q++) cp16(&Bb[c][oB[q]], pB[q] + c * 64);
        asm volatile("cp.async.commit_group;" ::: "memory");
    }
    const int NC = In / 64;  // 44
    for (int i = 0; i < NC; i++) {
        const int s = i & 1;
        asm volatile("cp.async.wait_group 1;" ::: "memory");
        __syncthreads();
        const __half* A = Ab[s];
        const __half* B = Bb[s];
#pragma unroll
        for (int ks = 0; ks < 4; ks++) {
            int k0 = ks * 16;
            uint32_t af[4][4], bf[8][2];
#pragma unroll
            for (int mi = 0; mi < 4; mi++) {
                int r = mBase + mi * 16 + qr;
                af[mi][0] = lds32(A, r * 72 + k0 + qc * 2);
                af[mi][1] = lds32(A, (r + 8) * 72 + k0 + qc * 2);
                af[mi][2] = lds32(A, r * 72 + k0 + qc * 2 + 8);
                af[mi][3] = lds32(A, (r + 8) * 72 + k0 + qc * 2 + 8);
            }
#pragma unroll
            for (int ni = 0; ni < 8; ni++) {
                int c = nBase + ni * 8 + qr;
                bf[ni][0] = lds32(B, c * 72 + k0 + qc * 2);
                bf[ni][1] = lds32(B, c * 72 + k0 + qc * 2 + 8);
            }
#pragma unroll
            for (int mi = 0; mi < 4; mi++)
#pragma unroll
                for (int ni = 0; ni < 8; ni++) mma16(acc[mi][ni], af[mi], bf[ni]);
        }
        __syncthreads();
        if (i + 2 < NC) {
#pragma unroll
            for (int q = 0; q < 4; q++) cp16(&Ab[s][oA[q]], pA[q] + (i + 2) * 64);
#pragma unroll
            for (int q = 0; q < 8; q++) cp16(&Bb[s][oB[q]], pB[q] + (i + 2) * 64);
        }
        asm volatile("cp.async.commit_group;" ::: "memory");
    }

    // ---- epilogue: scale by router weight, write per-pair output -------------
    const size_t rowBase = (size_t)mtile * 128;
#pragma unroll
    for (int mi = 0; mi < 4; mi++) {
#pragma unroll
        for (int half = 0; half < 2; half++) {
            int r = mBase + mi * 16 + qr + half * 8;
            float wt = g_wt[rowBase + r];
#pragma unroll
            for (int ni = 0; ni < 8; ni++) {
                int c = nBase + ni * 8 + qc * 2;
                float2 v;
                v.x = wt * acc[mi][ni][half * 2];
                v.y = wt * acc[mi][ni][half * 2 + 1];
                *(float2*)&g_po[(rowBase + r) * Hn + (size_t)n0 + c] = v;
            }
        }
    }
}

// ------------------- combine: out[t] = po[slot0] + po[slot1] ------------------
__global__ void k_combine(float* __restrict__ out) {
    int t = blockIdx.x;
    int i = threadIdx.x;
    int s0 = g_slots[2 * t], s1 = g_slots[2 * t + 1];
    float4 a = *(const float4*)&g_po[(size_t)s0 * Hn + i * 4];
    float4 b = *(const float4*)&g_po[(size_t)s1 * Hn + i * 4];
    float4 o;
    o.x = a.x + b.x; o.y = a.y + b.y; o.z = a.z + b.z; o.w = a.w + b.w;
    *(float4*)&out[(size_t)t * Hn + i * 4] = o;
}

// ------------------- launcher -------------------------------------------------
extern "C" void kernel_launch(void* const* d_in, const int* in_sizes, int n_in,
                              void* d_out, int out_size) {
    const float* x      = (const float*)d_in[0];
    const float* logits = (const float*)d_in[1];
    const float* w13    = (const float*)d_in[2];
    const float* w2     = (const float*)d_in[3];
    float* out = (float*)d_out;

    cudaFuncSetAttribute(k_gemm1, cudaFuncAttributeMaxDynamicSharedMemorySize, SMEM_BYTES);
    cudaFuncSetAttribute(k_gemm2, cudaFuncAttributeMaxDynamicSharedMemorySize, SMEM_BYTES);

    k_cvtw<<<2048, 256>>>(w13, w2);
    k_init<<<68, 256>>>();
    k_router<<<Tn / 256, 256>>>(logits);
    k_off<<<1, 32>>>();
    k_scatter<<<Tn / 256, 256>>>();
    k_gather<<<MAXP, 256>>>(x);
    k_gemm1<<<dim3(MAXP / 128, In / 128), 256, SMEM_BYTES>>>();  // (136, 22)
    k_gemm2<<<dim3(Hn / 256, MAXP / 128), 256, SMEM_BYTES>>>();  // (4, 136)
    k_combine<<<Tn, 256>>>(out);
}

// round 8
// speedup vs baseline: 1.9347x; 1.0689x over previous
#include <cuda_runtime.h>
#include <cuda_fp16.h>
#include <cstdint>

#define Tn 8192
#define Hn 1024
#define In 2816
#define En 8
#define MAXP 17408  // 16384 pairs + per-expert 128-alignment padding

// ------------------- device scratch (no allocations allowed) -----------------
__device__ int    g_cnt[En];
__device__ int    g_cur[En];
__device__ int    g_off[En + 1];
__device__ int    g_eid[Tn * 2];
__device__ float  g_ew[Tn * 2];
__device__ int    g_tok[MAXP];
__device__ float  g_wt[MAXP];
__device__ int    g_slots[Tn * 2];
__device__ __half g_xh[(size_t)MAXP * Hn];           // gathered x rows, fp16
__device__ __half g_hbh[(size_t)MAXP * In];          // silu(gate)*up, fp16
__device__ float  g_po[(size_t)MAXP * Hn];           // per-pair weighted output
__device__ __half g_w13h[(size_t)En * 2 * In * Hn];  // fp16 w13 (92MB)
__device__ __half g_w2h[(size_t)En * Hn * In];       // fp16 w2  (46MB)

// ------------------- helpers -------------------------------------------------
__device__ __forceinline__ uint32_t smem_u32(const void* p) {
    uint32_t a;
    asm("{ .reg .u64 t; cvta.to.shared.u64 t, %1; cvt.u32.u64 %0, t; }" : "=r"(a) : "l"(p));
    return a;
}
__device__ __forceinline__ void cp16(uint32_t saddr, const void* gsrc) {
    asm volatile("cp.async.cg.shared.global [%0], [%1], 16;\n" :: "r"(saddr), "l"(gsrc));
}
// fp16 m16n8k16 mma, fp32 accumulate
__device__ __forceinline__ void mma16(float* c, const uint32_t* a, const uint32_t* b) {
    asm volatile(
        "mma.sync.aligned.m16n8k16.row.col.f32.f16.f16.f32 "
        "{%0,%1,%2,%3}, {%4,%5,%6,%7}, {%8,%9}, {%0,%1,%2,%3};\n"
        : "+f"(c[0]), "+f"(c[1]), "+f"(c[2]), "+f"(c[3])
        : "r"(a[0]), "r"(a[1]), "r"(a[2]), "r"(a[3]), "r"(b[0]), "r"(b[1]));
}
__device__ __forceinline__ void ldm4(uint32_t* r, uint32_t addr) {
    asm volatile("ldmatrix.sync.aligned.m8n8.x4.shared.b16 {%0,%1,%2,%3}, [%4];"
                 : "=r"(r[0]), "=r"(r[1]), "=r"(r[2]), "=r"(r[3]) : "r"(addr));
}

// smem per stage (halves): A 128x72 = 9216, B 256x72 = 18432 -> 27648 (55296 B)
static constexpr int STG_H = 27648;               // halves per stage
static constexpr int STG_B = STG_H * 2;           // bytes per stage
static constexpr int BOFF_B = 9216 * 2;           // B offset within stage (bytes)
static constexpr int SMEM_BYTES = STG_B * 3;      // 165,888 B (3 stages)

// ------------------- kernel: convert weights to fp16 (+ state init) ----------
__global__ void k_cvtw(const float* __restrict__ w13, const float* __restrict__ w2) {
    long gid = (long)blockIdx.x * blockDim.x + threadIdx.x;
    if (gid < En) { g_cnt[gid] = 0; g_cur[gid] = 0; }
    const long stride = (long)gridDim.x * blockDim.x;
    for (long s = gid; s < MAXP; s += stride) {
        g_tok[s] = -1;
        g_wt[s] = 0.0f;
    }
    const long N1 = (long)En * 2 * In * Hn / 4;
    const long N2 = (long)En * Hn * In / 4;
    for (long i = gid; i < N1 + N2; i += stride) {
        float4 v = (i < N1) ? ((const float4*)w13)[i] : ((const float4*)w2)[i - N1];
        __half2 lo = __floats2half2_rn(v.x, v.y);
        __half2 hi = __floats2half2_rn(v.z, v.w);
        uint2 pk = { *(uint32_t*)&lo, *(uint32_t*)&hi };
        if (i < N1) ((uint2*)g_w13h)[i] = pk;
        else        ((uint2*)g_w2h)[i - N1] = pk;
    }
}

// ------------------- kernel: router ------------------------------------------
__global__ void k_router(const float* __restrict__ logits) {
    int t = blockIdx.x * blockDim.x + threadIdx.x;
    if (t >= Tn) return;
    float v[En];
#pragma unroll
    for (int e = 0; e < En; e++) v[e] = logits[t * En + e];
    int b0 = 0; float m0 = v[0];
#pragma unroll
    for (int e = 1; e < En; e++) if (v[e] > m0) { m0 = v[e]; b0 = e; }
    int b1 = -1; float m1 = -3.0e38f;
#pragma unroll
    for (int e = 0; e < En; e++) if (e != b0 && v[e] > m1) { m1 = v[e]; b1 = e; }
    float e1 = expf(m1 - m0);
    float inv = 1.0f / (1.0f + e1);
    g_eid[2 * t] = b0;     g_ew[2 * t] = inv;
    g_eid[2 * t + 1] = b1; g_ew[2 * t + 1] = e1 * inv;
    atomicAdd(&g_cnt[b0], 1);
    atomicAdd(&g_cnt[b1], 1);
}

// ------------------- kernel: 128-aligned offsets ------------------------------
__global__ void k_off() {
    if (threadIdx.x == 0 && blockIdx.x == 0) {
        int o = 0;
        g_off[0] = 0;
        for (int e = 0; e < En; e++) {
            o += (g_cnt[e] + 127) & ~127;
            g_off[e + 1] = o;
        }
    }
}

// ------------------- kernel: scatter ------------------------------------------
__global__ void k_scatter() {
    int t = blockIdx.x * blockDim.x + threadIdx.x;
    if (t >= Tn) return;
#pragma unroll
    for (int k = 0; k < 2; k++) {
        int e = g_eid[2 * t + k];
        int pos = atomicAdd(&g_cur[e], 1);
        int s = g_off[e] + pos;
        g_tok[s] = t;
        g_wt[s] = g_ew[2 * t + k];
        g_slots[2 * t + k] = s;
    }
}

// ------------------- kernel: gather x rows -> fp16 ----------------------------
__global__ void k_gather(const float* __restrict__ x) {
    int s = blockIdx.x;
    int tok = g_tok[s];
    uint2 pk = { 0u, 0u };
    if (tok >= 0) {
        float4 v = *(const float4*)&x[(size_t)tok * Hn + threadIdx.x * 4];
        __half2 lo = __floats2half2_rn(v.x, v.y);
        __half2 hi = __floats2half2_rn(v.z, v.w);
        pk.x = *(uint32_t*)&lo;
        pk.y = *(uint32_t*)&hi;
    }
    *(uint2*)&g_xh[(size_t)s * Hn + threadIdx.x * 4] = pk;
}

// =============================================================================
// Shared GEMM mainloop pieces.
// CTA tile M=128 x 256 B-rows, fp16 m16n8k16, K-chunk = 64 halves (128 B/row),
// pitch-72 smem rows, 3-stage cp.async pipeline, ldmatrix fragment loads.
// 8 warps of 64x64 (warp m = (w&1)*64, n = (w>>1)*64).
// =============================================================================

// per-lane ldmatrix address offset (bytes) within a 4-matrix 16x16 group:
// lanes 0-7: rows +0..7 col+0 | 8-15: rows +8..15 col+0
// 16-23: rows +0..7 col+8 | 24-31: rows +8..15 col+8   (halves)
__device__ __forceinline__ int ldm_lane_off(int lane) {
    int lr = lane & 7, grp = lane >> 3;
    int rowoff = lr + (grp & 1) * 8;
    int coloff = (grp >> 1) * 8;
    return (rowoff * 72 + coloff) * 2;
}

#define GEMM_MAINLOOP(NC)                                                          \
    /* prologue: fill stages 0,1,2 */                                              \
    _Pragma("unroll")                                                              \
    for (int c = 0; c < 3; c++) {                                                  \
        _Pragma("unroll")                                                          \
        for (int q = 0; q < 4; q++) cp16(sAo[q] + c * STG_B, pA[q] + c * 64);      \
        _Pragma("unroll")                                                          \
        for (int q = 0; q < 8; q++) cp16(sBo[q] + c * STG_B, pB[q] + c * 64);      \
        asm volatile("cp.async.commit_group;" ::: "memory");                       \
    }                                                                              \
    int st = 0;                                                                    \
    for (int i = 0; i < (NC); i++) {                                               \
        asm volatile("cp.async.wait_group 2;" ::: "memory");                       \
        __syncthreads();                                                           \
        const uint32_t aS = sbA + st * STG_B;                                      \
        const uint32_t bS = sbB + st * STG_B;                                      \
        _Pragma("unroll")                                                          \
        for (int ks = 0; ks < 4; ks++) {                                           \
            const int k0b = ks * 16 * 2;                                           \
            uint32_t af[4][4], bf[8][2];                                           \
            _Pragma("unroll")                                                      \
            for (int mi = 0; mi < 4; mi++)                                         \
                ldm4(af[mi], aS + (mBase + mi * 16) * 144 + k0b + loff);           \
            _Pragma("unroll")                                                      \
            for (int nj = 0; nj < 4; nj++) {                                       \
                uint32_t t4[4];                                                    \
                ldm4(t4, bS + (nBase + nj * 16) * 144 + k0b + loff);               \
                bf[nj * 2][0] = t4[0]; bf[nj * 2 + 1][0] = t4[1];                  \
                bf[nj * 2][1] = t4[2]; bf[nj * 2 + 1][1] = t4[3];                  \
            }                                                                      \
            _Pragma("unroll")                                                      \
            for (int mi = 0; mi < 4; mi++)                                         \
                _Pragma("unroll")                                                  \
                for (int ni = 0; ni < 8; ni++) mma16(acc[mi][ni], af[mi], bf[ni]); \
        }                                                                          \
        __syncthreads();                                                           \
        if (i + 3 < (NC)) {                                                        \
            _Pragma("unroll")                                                      \
            for (int q = 0; q < 4; q++) cp16(sAo[q] + st * STG_B, pA[q] + (i + 3) * 64); \
            _Pragma("unroll")                                                      \
            for (int q = 0; q < 8; q++) cp16(sBo[q] + st * STG_B, pB[q] + (i + 3) * 64); \
        }                                                                          \
        asm volatile("cp.async.commit_group;" ::: "memory");                       \
        if (++st == 3) st = 0;                                                     \
    }

// =============================================================================
// GEMM1: h = silu(x W1^T) * (x W3^T). B-rows 0..127 = gate, 128..255 = up.
// =============================================================================
__global__ __launch_bounds__(256, 1) void k_gemm1() {
    extern __shared__ __align__(16) char smraw[];
    const int mtile = blockIdx.x, ntile = blockIdx.y;  // mtile fast (A L2-reuse)
    if (mtile * 128 >= g_off[En]) return;
    int e = 0;
#pragma unroll
    for (int i = 0; i < En; i++) if (mtile * 128 >= g_off[i + 1]) e = i + 1;
    const int n0 = ntile * 128;
    const int tid = threadIdx.x;

    const uint32_t sb = smem_u32(smraw);
    const uint32_t sbA = sb, sbB = sb + BOFF_B;

    // loader slots: A 4x16B/thread/chunk, B 8x16B/thread/chunk
    const __half* pA[4]; uint32_t sAo[4];
    const __half* pB[8]; uint32_t sBo[8];
#pragma unroll
    for (int q = 0; q < 4; q++) {
        int u = tid + q * 256, r = u >> 3, sg = u & 7;
        pA[q] = g_xh + (size_t)(mtile * 128 + r) * Hn + sg * 8;
        sAo[q] = sbA + (r * 72 + sg * 8) * 2;
    }
#pragma unroll
    for (int q = 0; q < 8; q++) {
        int u = tid + q * 256, r = u >> 3, sg = u & 7;
        pB[q] = (r < 128)
            ? (g_w13h + ((size_t)e * 2 * In + n0 + r) * Hn + sg * 8)
            : (g_w13h + ((size_t)e * 2 * In + In + n0 + (r - 128)) * Hn + sg * 8);
        sBo[q] = sbB + (r * 72 + sg * 8) * 2;
    }

    const int w = tid >> 5, lane = tid & 31;
    const int mBase = (w & 1) * 64, nBase = (w >> 1) * 64;
    const int qr = lane >> 2, qc = lane & 3;
    const int loff = ldm_lane_off(lane);

    float acc[4][8][4];
#pragma unroll
    for (int a = 0; a < 4; a++)
#pragma unroll
        for (int b = 0; b < 8; b++)
#pragma unroll
            for (int c = 0; c < 4; c++) acc[a][b][c] = 0.0f;

    GEMM_MAINLOOP(Hn / 64)

    // ---- epilogue: gate warps stage to smem; up warps compute silu(g)*u ------
    float* sE = (float*)smraw;  // 128 x pitch-130 floats = 66,560 B (fits)
    if (nBase < 128) {
#pragma unroll
        for (int mi = 0; mi < 4; mi++)
#pragma unroll
            for (int ni = 0; ni < 8; ni++) {
                int r = mBase + mi * 16 + qr;
                int c = nBase + ni * 8 + qc * 2;
                sE[r * 130 + c] = acc[mi][ni][0];
                sE[r * 130 + c + 1] = acc[mi][ni][1];
                sE[(r + 8) * 130 + c] = acc[mi][ni][2];
                sE[(r + 8) * 130 + c + 1] = acc[mi][ni][3];
            }
    }
    __syncthreads();
    if (nBase >= 128) {
        const size_t rowBase = (size_t)mtile * 128;
#pragma unroll
        for (int mi = 0; mi < 4; mi++)
#pragma unroll
            for (int ni = 0; ni < 8; ni++) {
                int j = (nBase - 128) + ni * 8 + qc * 2;
#pragma unroll
                for (int half = 0; half < 2; half++) {
                    int r = mBase + mi * 16 + qr + half * 8;
                    float g0 = sE[r * 130 + j];
                    float g1 = sE[r * 130 + j + 1];
                    float u0 = acc[mi][ni][half * 2];
                    float u1 = acc[mi][ni][half * 2 + 1];
                    float h0 = g0 * (1.0f / (1.0f + __expf(-g0))) * u0;
                    float h1 = g1 * (1.0f / (1.0f + __expf(-g1))) * u1;
                    __half2 hv = __floats2half2_rn(h0, h1);
                    *(__half2*)&g_hbh[(rowBase + r) * In + (size_t)n0 + j] = hv;
                }
            }
    }
}

// =============================================================================
// GEMM2: po = wt * (h W2^T).  CTA tile M=128 x N=256 out cols, K = In.
// =============================================================================
__global__ __launch_bounds__(256, 1) void k_gemm2() {
    extern __shared__ __align__(16) char smraw[];
    const int ntile = blockIdx.x, mtile = blockIdx.y;  // ntile fast (w2 L2-resident)
    if (mtile * 128 >= g_off[En]) return;
    int e = 0;
#pragma unroll
    for (int i = 0; i < En; i++) if (mtile * 128 >= g_off[i + 1]) e = i + 1;
    const int n0 = ntile * 256;
    const int tid = threadIdx.x;

    const uint32_t sb = smem_u32(smraw);
    const uint32_t sbA = sb, sbB = sb + BOFF_B;

    const __half* pA[4]; uint32_t sAo[4];
    const __half* pB[8]; uint32_t sBo[8];
#pragma unroll
    for (int q = 0; q < 4; q++) {
        int u = tid + q * 256, r = u >> 3, sg = u & 7;
        pA[q] = g_hbh + (size_t)(mtile * 128 + r) * In + sg * 8;
        sAo[q] = sbA + (r * 72 + sg * 8) * 2;
    }
#pragma unroll
    for (int q = 0; q < 8; q++) {
        int u = tid + q * 256, r = u >> 3, sg = u & 7;
        pB[q] = g_w2h + ((size_t)e * Hn + n0 + r) * In + sg * 8;
        sBo[q] = sbB + (r * 72 + sg * 8) * 2;
    }

    const int w = tid >> 5, lane = tid & 31;
    const int mBase = (w & 1) * 64, nBase = (w >> 1) * 64;
    const int qr = lane >> 2, qc = lane & 3;
    const int loff = ldm_lane_off(lane);

    float acc[4][8][4];
#pragma unroll
    for (int a = 0; a < 4; a++)
#pragma unroll
        for (int b = 0; b < 8; b++)
#pragma unroll
            for (int c = 0; c < 4; c++) acc[a][b][c] = 0.0f;

    GEMM_MAINLOOP(In / 64)

    // ---- epilogue: scale by router weight, write per-pair output -------------
    const size_t rowBase = (size_t)mtile * 128;
#pragma unroll
    for (int mi = 0; mi < 4; mi++) {
#pragma unroll
        for (int half = 0; half < 2; half++) {
            int r = mBase + mi * 16 + qr + half * 8;
            float wt = g_wt[rowBase + r];
#pragma unroll
            for (int ni = 0; ni < 8; ni++) {
                int c = nBase + ni * 8 + qc * 2;
                float2 v;
                v.x = wt * acc[mi][ni][half * 2];
                v.y = wt * acc[mi][ni][half * 2 + 1];
                *(float2*)&g_po[(rowBase + r) * Hn + (size_t)n0 + c] = v;
            }
        }
    }
}

// ------------------- combine: out[t] = po[slot0] + po[slot1] ------------------
__global__ void k_combine(float* __restrict__ out) {
    int t = blockIdx.x;
    int i = threadIdx.x;
    int s0 = g_slots[2 * t], s1 = g_slots[2 * t + 1];
    float4 a = *(const float4*)&g_po[(size_t)s0 * Hn + i * 4];
    float4 b = *(const float4*)&g_po[(size_t)s1 * Hn + i * 4];
    float4 o;
    o.x = a.x + b.x; o.y = a.y + b.y; o.z = a.z + b.z; o.w = a.w + b.w;
    *(float4*)&out[(size_t)t * Hn + i * 4] = o;
}

// ------------------- launcher -------------------------------------------------
extern "C" void kernel_launch(void* const* d_in, const int* in_sizes, int n_in,
                              void* d_out, int out_size) {
    const float* x      = (const float*)d_in[0];
    const float* logits = (const float*)d_in[1];
    const float* w13    = (const float*)d_in[2];
    const float* w2     = (const float*)d_in[3];
    float* out = (float*)d_out;

    cudaFuncSetAttribute(k_gemm1, cudaFuncAttributeMaxDynamicSharedMemorySize, SMEM_BYTES);
    cudaFuncSetAttribute(k_gemm2, cudaFuncAttributeMaxDynamicSharedMemorySize, SMEM_BYTES);

    k_cvtw<<<2048, 256>>>(w13, w2);      // weights -> fp16, plus state init
    k_router<<<Tn / 256, 256>>>(logits);
    k_off<<<1, 32>>>();
    k_scatter<<<Tn / 256, 256>>>();
    k_gather<<<MAXP, 256>>>(x);
    k_gemm1<<<dim3(MAXP / 128, In / 128), 256, SMEM_BYTES>>>();  // (136, 22)
    k_gemm2<<<dim3(Hn / 256, MAXP / 128), 256, SMEM_BYTES>>>();  // (4, 136)
    k_combine<<<Tn, 256>>>(out);
}